// round 3
// baseline (speedup 1.0000x reference)
#include <cuda_runtime.h>
#include <math.h>
#include <stdint.h>

// ---------------- problem constants ----------------
#define BNODES   4096      // B*N
#define HDIM     256
#define EMAX     16384

// ---------------- scratch (device globals, no allocs) ----------------
__device__ float g_h   [BNODES*HDIM];
__device__ float g_ht  [BNODES*HDIM];
__device__ float g_Hm  [BNODES*HDIM];
__device__ float g_agg [BNODES*HDIM];
__device__ float g_embg[BNODES*HDIM];
__device__ float g_A   [BNODES*HDIM];
__device__ float g_B   [BNODES*HDIM];
__device__ float g_WfoldT[5*HDIM];   // [c][k]
__device__ float g_bfold[8];
__device__ float g_propadd[64*HDIM]; // includes b_add
__device__ double g_acc;

// ---------------- helpers ----------------
__device__ __forceinline__ uint32_t f2tf32(float x) {
    uint32_t r;
    asm("cvt.rna.tf32.f32 %0, %1;" : "=r"(r) : "f"(x));
    return r;
}

__device__ __forceinline__ void mma_tf32(float& d0, float& d1, float& d2, float& d3,
                                         uint32_t a0, uint32_t a1, uint32_t a2, uint32_t a3,
                                         uint32_t b0, uint32_t b1)
{
    asm volatile(
        "mma.sync.aligned.m16n8k8.row.col.f32.tf32.tf32.f32 "
        "{%0,%1,%2,%3}, {%4,%5,%6,%7}, {%8,%9}, {%0,%1,%2,%3};"
        : "+f"(d0), "+f"(d1), "+f"(d2), "+f"(d3)
        : "r"(a0), "r"(a1), "r"(a2), "r"(a3), "r"(b0), "r"(b1));
}

// ---------------- setup: folds + property conditioning ----------------
__global__ void setup_kernel(const float* __restrict__ W3, const float* __restrict__ b3,
                             const float* __restrict__ W_out, const float* __restrict__ b_out,
                             const float* __restrict__ props, const float* __restrict__ W_prop,
                             const float* __restrict__ b_prop, const float* __restrict__ W_add,
                             const float* __restrict__ b_add)
{
    int t = threadIdx.x;   // 0..255
    {
        float s[5] = {0.f,0.f,0.f,0.f,0.f};
        for (int j = 0; j < 512; j++) {
            float w3 = W3[t*512 + j];
            #pragma unroll
            for (int c = 0; c < 5; c++) s[c] += w3 * W_out[j*5 + c];
        }
        #pragma unroll
        for (int c = 0; c < 5; c++) g_WfoldT[c*256 + t] = s[c];
    }
    if (t < 5) {
        float s = b_out[t];
        for (int k = 0; k < 512; k++) s += b3[k] * W_out[k*5 + t];
        g_bfold[t] = s;
    }
    for (int b = 0; b < 64; b++) {
        float pv = props[b];
        float s = b_add[t];
        for (int p = 0; p < 64; p++) {
            float pe = pv * W_prop[p] + b_prop[p];
            s += pe * W_add[(256 + p)*256 + t];
        }
        g_propadd[b*256 + t] = s;
    }
    if (t == 0) g_acc = 0.0;
}

// ---------------- tf32 tensor-core SGEMM ----------------
// C[4096,256] = act(A1@W1 [+ A2@W2] + bias [+ rowBias])
// BM=32, BN=64, BK=32, 128 threads (4 warps, 2m x 2n), warp tile 16x32.
// Grid (4, 128) = 512 CTAs for occupancy. Register prefetch of next k-block.
__global__ void __launch_bounds__(128)
sgemm_tc(const float* __restrict__ A1, const float* __restrict__ W1, int K1,
         const float* __restrict__ A2, const float* __restrict__ W2, int K2,
         const float* __restrict__ bias, const float* __restrict__ rowBias,
         float* __restrict__ C, int doRelu)
{
    __shared__ uint32_t As[32][36];    // [k][m], tf32
    __shared__ uint32_t Ws[32][68];    // [k][n], tf32

    int tid = threadIdx.x;
    int wid = tid >> 5;
    int lane = tid & 31;
    int warp_m = wid & 1;              // 0..1 -> 16 rows
    int warp_n = wid >> 1;             // 0..1 -> 32 cols
    int gi = lane >> 2;                // 0..7
    int tg = lane & 3;                 // 0..3

    int m0 = blockIdx.y * 32;
    int n0 = blockIdx.x * 64;

    float acc[4][4];
    #pragma unroll
    for (int nt = 0; nt < 4; nt++)
        #pragma unroll
        for (int q = 0; q < 4; q++) acc[nt][q] = 0.f;

    // A-load indices (2 float4 per thread): f = tid + i*128 -> row=f>>3, kq=(f&7)*4
    int a_row[2], a_kq[2];
    #pragma unroll
    for (int i = 0; i < 2; i++) { int f = tid + i*128; a_row[i] = f >> 3; a_kq[i] = (f & 7) * 4; }
    // W-load indices (4 float4 per thread): f = tid + i*128 -> k=f>>4, nq=(f&15)*4
    int w_k[4], w_nq[4];
    #pragma unroll
    for (int i = 0; i < 4; i++) { int f = tid + i*128; w_k[i] = f >> 4; w_nq[i] = (f & 15) * 4; }

    for (int pass = 0; pass < 2; pass++) {
        const float* A = pass ? A2 : A1;
        const float* W = pass ? W2 : W1;
        int K = pass ? K2 : K1;
        if (K == 0) break;
        int nit = K >> 5;

        float4 pa[2], pw[4];
        // initial load (iter 0)
        #pragma unroll
        for (int i = 0; i < 2; i++)
            pa[i] = *(const float4*)&A[(size_t)(m0 + a_row[i])*K + a_kq[i]];
        #pragma unroll
        for (int i = 0; i < 4; i++)
            pw[i] = *(const float4*)&W[(size_t)w_k[i]*256 + n0 + w_nq[i]];

        for (int it = 0; it < nit; it++) {
            __syncthreads();
            // stage regs -> smem (tf32 convert)
            #pragma unroll
            for (int i = 0; i < 2; i++) {
                As[a_kq[i]+0][a_row[i]] = f2tf32(pa[i].x);
                As[a_kq[i]+1][a_row[i]] = f2tf32(pa[i].y);
                As[a_kq[i]+2][a_row[i]] = f2tf32(pa[i].z);
                As[a_kq[i]+3][a_row[i]] = f2tf32(pa[i].w);
            }
            #pragma unroll
            for (int i = 0; i < 4; i++) {
                Ws[w_k[i]][w_nq[i]+0] = f2tf32(pw[i].x);
                Ws[w_k[i]][w_nq[i]+1] = f2tf32(pw[i].y);
                Ws[w_k[i]][w_nq[i]+2] = f2tf32(pw[i].z);
                Ws[w_k[i]][w_nq[i]+3] = f2tf32(pw[i].w);
            }
            __syncthreads();
            // prefetch next iter (overlaps with MMA below)
            if (it + 1 < nit) {
                int k0n = (it + 1) << 5;
                #pragma unroll
                for (int i = 0; i < 2; i++)
                    pa[i] = *(const float4*)&A[(size_t)(m0 + a_row[i])*K + k0n + a_kq[i]];
                #pragma unroll
                for (int i = 0; i < 4; i++)
                    pw[i] = *(const float4*)&W[(size_t)(k0n + w_k[i])*256 + n0 + w_nq[i]];
            }
            // MMA
            #pragma unroll
            for (int ks = 0; ks < 4; ks++) {
                int kb = ks*8;
                int m = warp_m*16 + gi;
                uint32_t a0 = As[kb + tg    ][m];
                uint32_t a1 = As[kb + tg    ][m + 8];
                uint32_t a2 = As[kb + tg + 4][m];
                uint32_t a3 = As[kb + tg + 4][m + 8];
                #pragma unroll
                for (int nt = 0; nt < 4; nt++) {
                    int n = warp_n*32 + nt*8 + gi;
                    uint32_t b0 = Ws[kb + tg    ][n];
                    uint32_t b1 = Ws[kb + tg + 4][n];
                    mma_tf32(acc[nt][0], acc[nt][1], acc[nt][2], acc[nt][3],
                             a0, a1, a2, a3, b0, b1);
                }
            }
        }
    }

    // epilogue
    int row0 = m0 + warp_m*16 + gi;
    int row1 = row0 + 8;
    #pragma unroll
    for (int nt = 0; nt < 4; nt++) {
        int n = n0 + warp_n*32 + nt*8 + tg*2;
        float v00 = acc[nt][0], v01 = acc[nt][1];   // row0
        float v10 = acc[nt][2], v11 = acc[nt][3];   // row1
        if (bias) { float b0 = bias[n], b1 = bias[n+1]; v00 += b0; v01 += b1; v10 += b0; v11 += b1; }
        if (rowBias) {
            const float* rb0 = rowBias + ((row0 >> 6) << 8);
            const float* rb1 = rowBias + ((row1 >> 6) << 8);
            v00 += rb0[n]; v01 += rb0[n+1];
            v10 += rb1[n]; v11 += rb1[n+1];
        }
        if (doRelu) {
            v00 = fmaxf(v00, 0.f); v01 = fmaxf(v01, 0.f);
            v10 = fmaxf(v10, 0.f); v11 = fmaxf(v11, 0.f);
        }
        *(float2*)&C[(size_t)row0*256 + n] = make_float2(v00, v01);
        *(float2*)&C[(size_t)row1*256 + n] = make_float2(v10, v11);
    }
}

// ---------------- edge scatter: agg[dst] += relu(Hm[src] + b_msg + ea@We) ----------
// We (5x256) lives in SMEM; EAW never materialized.
__global__ void __launch_bounds__(256)
edge_scatter(const int* __restrict__ src, const int* __restrict__ dst,
             const float* __restrict__ ea, const float* __restrict__ W_msg,
             const float* __restrict__ b_msg, const float* __restrict__ Hm,
             float* __restrict__ agg, int E)
{
    __shared__ float We[5][256];
    __shared__ float bm[256];
    __shared__ float eas[32][5];
    __shared__ int   ss[32], ds[32];
    int tid = threadIdx.x;
    const float* Wep = W_msg + 256*256;
    for (int i = tid; i < 5*256; i += 256) ((float*)We)[i] = Wep[i];
    bm[tid] = b_msg[tid];
    int e0 = blockIdx.x * 32;
    if (tid < 32 && e0 + tid < E) { ss[tid] = src[e0+tid]; ds[tid] = dst[e0+tid]; }
    if (tid >= 64 && tid < 64 + 160) {
        int i = tid - 64;
        if (e0*5 + i < E*5) eas[i/5][i%5] = ea[(size_t)e0*5 + i];
    }
    __syncthreads();
    #pragma unroll 4
    for (int q = 0; q < 32; q++) {
        int e = e0 + q;
        if (e >= E) break;
        float v = bm[tid]
                + eas[q][0]*We[0][tid] + eas[q][1]*We[1][tid] + eas[q][2]*We[2][tid]
                + eas[q][3]*We[3][tid] + eas[q][4]*We[4][tid]
                + Hm[(size_t)ss[q]*256 + tid];
        v = fmaxf(v, 0.f);
        atomicAdd(&agg[(size_t)ds[q]*256 + tid], v);
    }
}

// ---------------- pair megakernel (tensor-core h2 GEMM) ----------------
__global__ void __launch_bounds__(256, 2)
pair_kernel(const float* __restrict__ Ag, const float* __restrict__ Bg,
            const int* __restrict__ sel_b, const int* __restrict__ sel_i,
            const int* __restrict__ sel_j, const int* __restrict__ golden,
            const float* __restrict__ W2, const float* __restrict__ b2)
{
    extern __shared__ uint32_t smem[];
    uint32_t* h1u = smem;                   // [64][260] tf32, reused as fp32 h2
    uint32_t* w2u = h1u + 64*260;           // [32][260] tf32
    float*    wfs = (float*)(w2u + 32*260); // [5][256]
    float*    b2s = wfs + 5*256;            // [256]
    float*    bfs = b2s + 256;              // [8]
    float*    h1f = (float*)h1u;

    int tid  = threadIdx.x;
    int wid  = tid >> 5;
    int lane = tid & 31;
    int warp_m = wid & 1;                  // 0..1
    int warp_n = wid >> 1;                 // 0..3
    int gi = lane >> 2;
    int tg = lane & 3;
    int e0 = blockIdx.x * 64;

    for (int i = tid; i < 5*256; i += 256) wfs[i] = g_WfoldT[i];
    b2s[tid] = b2[tid];
    if (tid < 5) bfs[tid] = g_bfold[tid];

    // gather phase: h1 = relu(A[bi*64+si] + B[bi*64+sj]), stored tf32 [row][260]
    #pragma unroll
    for (int t = 0; t < 8; t++) {
        int r = wid*8 + t;
        int e = e0 + r;
        int bsel = sel_b[e];
        int ii = bsel*64 + sel_i[e];
        int jj = bsel*64 + sel_j[e];
        const float* ap = Ag + (size_t)ii*256;
        const float* bp = Bg + (size_t)jj*256;
        #pragma unroll
        for (int q = 0; q < 2; q++) {
            int c = lane*4 + q*128;
            float4 av = *(const float4*)(ap + c);
            float4 bv = *(const float4*)(bp + c);
            h1u[r*260 + c + 0] = f2tf32(fmaxf(av.x + bv.x, 0.f));
            h1u[r*260 + c + 1] = f2tf32(fmaxf(av.y + bv.y, 0.f));
            h1u[r*260 + c + 2] = f2tf32(fmaxf(av.z + bv.z, 0.f));
            h1u[r*260 + c + 3] = f2tf32(fmaxf(av.w + bv.w, 0.f));
        }
    }
    __syncthreads();

    float acc[2][8][4];
    #pragma unroll
    for (int mt = 0; mt < 2; mt++)
        #pragma unroll
        for (int nt = 0; nt < 8; nt++)
            #pragma unroll
            for (int q = 0; q < 4; q++) acc[mt][nt][q] = 0.f;

    for (int k0 = 0; k0 < 256; k0 += 32) {
        #pragma unroll
        for (int i = 0; i < 8; i++) {
            int f  = tid + i*256;
            int k  = f >> 6;
            int nq = (f & 63) * 4;
            float4 v = *(const float4*)&W2[(size_t)(k0 + k)*256 + nq];
            w2u[k*260 + nq + 0] = f2tf32(v.x); w2u[k*260 + nq + 1] = f2tf32(v.y);
            w2u[k*260 + nq + 2] = f2tf32(v.z); w2u[k*260 + nq + 3] = f2tf32(v.w);
        }
        __syncthreads();
        #pragma unroll
        for (int ks = 0; ks < 4; ks++) {
            int kb = ks*8;
            uint32_t a[2][4];
            #pragma unroll
            for (int mt = 0; mt < 2; mt++) {
                int m = warp_m*32 + mt*16 + gi;
                a[mt][0] = h1u[(m    )*260 + k0 + kb + tg    ];
                a[mt][1] = h1u[(m + 8)*260 + k0 + kb + tg    ];
                a[mt][2] = h1u[(m    )*260 + k0 + kb + tg + 4];
                a[mt][3] = h1u[(m + 8)*260 + k0 + kb + tg + 4];
            }
            #pragma unroll
            for (int nt = 0; nt < 8; nt++) {
                int n = warp_n*64 + nt*8 + gi;
                uint32_t b0 = w2u[(kb + tg    )*260 + n];
                uint32_t b1 = w2u[(kb + tg + 4)*260 + n];
                #pragma unroll
                for (int mt = 0; mt < 2; mt++)
                    mma_tf32(acc[mt][nt][0], acc[mt][nt][1], acc[mt][nt][2], acc[mt][nt][3],
                             a[mt][0], a[mt][1], a[mt][2], a[mt][3], b0, b1);
            }
        }
        __syncthreads();
    }

    // h2 = relu(acc + b2)
    #pragma unroll
    for (int mt = 0; mt < 2; mt++) {
        #pragma unroll
        for (int half = 0; half < 2; half++) {
            int m = warp_m*32 + mt*16 + gi + half*8;
            #pragma unroll
            for (int nt = 0; nt < 8; nt++) {
                int n = warp_n*64 + nt*8 + tg*2;
                float v0 = fmaxf(acc[mt][nt][half*2 + 0] + b2s[n],     0.f);
                float v1 = fmaxf(acc[mt][nt][half*2 + 1] + b2s[n + 1], 0.f);
                h1f[m*260 + n]     = v0;
                h1f[m*260 + n + 1] = v1;
            }
        }
    }
    __syncthreads();

    // logits + loss
    double lsum = 0.0;
    for (int t = 0; t < 8; t++) {
        int r = wid*8 + t;
        float p[5] = {0.f,0.f,0.f,0.f,0.f};
        #pragma unroll
        for (int m8 = 0; m8 < 8; m8++) {
            int k = lane + 32*m8;
            float hv = h1f[r*260 + k];
            #pragma unroll
            for (int c = 0; c < 5; c++) p[c] += hv * wfs[c*256 + k];
        }
        #pragma unroll
        for (int off = 16; off; off >>= 1)
            #pragma unroll
            for (int c = 0; c < 5; c++) p[c] += __shfl_xor_sync(0xffffffffu, p[c], off);
        if (lane == 0) {
            float lg[5], mx = -1e30f;
            #pragma unroll
            for (int c = 0; c < 5; c++) { lg[c] = p[c] + bfs[c]; mx = fmaxf(mx, lg[c]); }
            float s = 0.f;
            #pragma unroll
            for (int c = 0; c < 5; c++) s += expf(lg[c] - mx);
            float lse = mx + logf(s);
            int gold = golden[e0 + r];
            lsum += (double)(lse - lg[gold]);
        }
    }
    if (lane == 0) atomicAdd(&g_acc, lsum);
}

// ---------------- finalize ----------------
__global__ void finalize_kernel(float* __restrict__ out, int esel)
{
    out[0] = (float)(g_acc / (double)esel);
}

// ---------------- host launcher ----------------
extern "C" void kernel_launch(void* const* d_in, const int* in_sizes, int n_in,
                              void* d_out, int out_size)
{
    const float* x         = (const float*)d_in[0];
    const int*   eidx      = (const int*)  d_in[1];
    const float* edge_attr = (const float*)d_in[2];
    const float* props     = (const float*)d_in[3];
    const int*   sel_b     = (const int*)  d_in[4];
    const int*   sel_i     = (const int*)  d_in[5];
    const int*   sel_j     = (const int*)  d_in[6];
    const int*   golden    = (const int*)  d_in[7];
    const float* W_prop = (const float*)d_in[8];
    const float* b_prop = (const float*)d_in[9];
    const float* W_in   = (const float*)d_in[10];
    const float* b_in   = (const float*)d_in[11];
    const float* W_msg  = (const float*)d_in[12];
    const float* b_msg  = (const float*)d_in[13];
    const float* W_upd  = (const float*)d_in[14];
    const float* b_upd  = (const float*)d_in[15];
    const float* W_add  = (const float*)d_in[16];
    const float* b_add  = (const float*)d_in[17];
    const float* W1     = (const float*)d_in[18];
    const float* b1     = (const float*)d_in[19];
    const float* W2     = (const float*)d_in[20];
    const float* b2     = (const float*)d_in[21];
    const float* W3     = (const float*)d_in[22];
    const float* b3     = (const float*)d_in[23];
    const float* W_out  = (const float*)d_in[24];
    const float* b_out  = (const float*)d_in[25];

    int E    = in_sizes[1] / 2;
    int ESEL = in_sizes[4];
    const int* src = eidx;
    const int* dst = eidx + E;

    float *p_h, *p_ht, *p_agg, *p_embg, *p_A, *p_B, *p_Hm, *p_propadd;
    cudaGetSymbolAddress((void**)&p_h,    g_h);
    cudaGetSymbolAddress((void**)&p_ht,   g_ht);
    cudaGetSymbolAddress((void**)&p_agg,  g_agg);
    cudaGetSymbolAddress((void**)&p_embg, g_embg);
    cudaGetSymbolAddress((void**)&p_A,    g_A);
    cudaGetSymbolAddress((void**)&p_B,    g_B);
    cudaGetSymbolAddress((void**)&p_Hm,   g_Hm);
    cudaGetSymbolAddress((void**)&p_propadd, g_propadd);

    int pairSmem = (64*260 + 32*260 + 5*256 + 256 + 8) * (int)sizeof(float);
    cudaFuncSetAttribute(pair_kernel, cudaFuncAttributeMaxDynamicSharedMemorySize, pairSmem);

    dim3 gemmGrid(4, BNODES/32);   // N=256/64, M=4096/32 -> 512 CTAs

    setup_kernel<<<1, 256>>>(W3, b3, W_out, b_out, props, W_prop, b_prop, W_add, b_add);

    // h0 = relu(x @ W_in + b_in)
    sgemm_tc<<<gemmGrid, 128>>>(x, W_in, 192, nullptr, nullptr, 0, b_in, nullptr, p_h, 1);

    float* cur = p_h;
    float* nxt = p_ht;
    for (int t = 0; t < 4; t++) {
        cudaMemsetAsync(p_agg, 0, (size_t)BNODES*HDIM*sizeof(float));
        // Hm = h @ W_msg[0:256]
        sgemm_tc<<<gemmGrid, 128>>>(cur, W_msg, 256, nullptr, nullptr, 0, nullptr, nullptr, p_Hm, 0);
        // agg[dst] += relu(Hm[src] + b_msg + ea@We)
        edge_scatter<<<(E + 31)/32, 256>>>(src, dst, edge_attr, W_msg, b_msg, p_Hm, p_agg, E);
        // h = relu(h@W_upd_top + agg@W_upd_bot + b_upd)
        sgemm_tc<<<gemmGrid, 128>>>(cur, W_upd, 256, p_agg, W_upd + 256*256, 256,
                                    b_upd, nullptr, nxt, 1);
        float* tmp = cur; cur = nxt; nxt = tmp;
    }

    // embg = h @ W_add[0:256] + propadd[b]   (no relu)
    sgemm_tc<<<gemmGrid, 128>>>(cur, W_add, 256, nullptr, nullptr, 0, nullptr, p_propadd, p_embg, 0);

    // A = embg @ W1[0:256] + b1 ; B = embg @ W1[256:512]
    sgemm_tc<<<gemmGrid, 128>>>(p_embg, W1, 256, nullptr, nullptr, 0, b1, nullptr, p_A, 0);
    sgemm_tc<<<gemmGrid, 128>>>(p_embg, W1 + 256*256, 256, nullptr, nullptr, 0, nullptr, nullptr, p_B, 0);

    // pair stage + loss
    pair_kernel<<<ESEL/64, 256, pairSmem>>>(p_A, p_B, sel_b, sel_i, sel_j, golden, W2, b2);

    finalize_kernel<<<1, 1>>>((float*)d_out, ESEL);
}

// round 4
// speedup vs baseline: 1.6903x; 1.6903x over previous
#include <cuda_runtime.h>
#include <math.h>
#include <stdint.h>

// ---------------- problem constants ----------------
#define BNODES   4096      // B*N
#define HDIM     256
#define EMAX     16384

// ---------------- scratch (device globals, no allocs) ----------------
__device__ float g_h   [BNODES*HDIM];
__device__ float g_ht  [BNODES*HDIM];
__device__ float g_Hm  [BNODES*HDIM];
__device__ float g_agg [BNODES*HDIM];
__device__ float g_embg[BNODES*HDIM];
__device__ float g_A   [BNODES*HDIM];
__device__ float g_B   [BNODES*HDIM];
__device__ float g_WfoldT[5*HDIM];   // [c][k]
__device__ float g_bfold[8];
__device__ float g_propadd[64*HDIM]; // includes b_add
__device__ double g_acc;

// ---------------- helpers ----------------
__device__ __forceinline__ void mma_tf32(float& d0, float& d1, float& d2, float& d3,
                                         uint32_t a0, uint32_t a1, uint32_t a2, uint32_t a3,
                                         uint32_t b0, uint32_t b1)
{
    asm volatile(
        "mma.sync.aligned.m16n8k8.row.col.f32.tf32.tf32.f32 "
        "{%0,%1,%2,%3}, {%4,%5,%6,%7}, {%8,%9}, {%0,%1,%2,%3};"
        : "+f"(d0), "+f"(d1), "+f"(d2), "+f"(d3)
        : "r"(a0), "r"(a1), "r"(a2), "r"(a3), "r"(b0), "r"(b1));
}

__device__ __forceinline__ void cp_async16(void* smem_ptr, const void* gmem_ptr)
{
    uint32_t s = (uint32_t)__cvta_generic_to_shared(smem_ptr);
    asm volatile("cp.async.cg.shared.global [%0], [%1], 16;" :: "r"(s), "l"(gmem_ptr));
}
__device__ __forceinline__ void cp_commit() { asm volatile("cp.async.commit_group;"); }
template<int N> __device__ __forceinline__ void cp_wait() {
    asm volatile("cp.async.wait_group %0;" :: "n"(N));
}

// ---------------- parallel setup ----------------
// blocks 0..63: propadd for batch b;  64..71: WfoldT (32 t per block);  72: bfold + acc
__global__ void __launch_bounds__(256)
setup_kernel(const float* __restrict__ W3, const float* __restrict__ b3,
             const float* __restrict__ W_out, const float* __restrict__ b_out,
             const float* __restrict__ props, const float* __restrict__ W_prop,
             const float* __restrict__ b_prop, const float* __restrict__ W_add,
             const float* __restrict__ b_add)
{
    int bid = blockIdx.x;
    int tid = threadIdx.x;
    if (bid < 64) {
        __shared__ float pe[64];
        if (tid < 64) pe[tid] = props[bid] * W_prop[tid] + b_prop[tid];
        __syncthreads();
        float s = b_add[tid];
        #pragma unroll 8
        for (int p = 0; p < 64; p++) s += pe[p] * W_add[(256 + p)*256 + tid];
        g_propadd[bid*256 + tid] = s;
    } else if (bid < 72) {
        // 32 t-values per block; 8 lanes per t
        int t = (bid - 64)*32 + (tid >> 3);
        int l = tid & 7;
        float s[5] = {0.f,0.f,0.f,0.f,0.f};
        for (int j = l; j < 512; j += 8) {
            float w3 = W3[t*512 + j];
            #pragma unroll
            for (int c = 0; c < 5; c++) s[c] += w3 * W_out[j*5 + c];
        }
        #pragma unroll
        for (int off = 4; off; off >>= 1)
            #pragma unroll
            for (int c = 0; c < 5; c++) s[c] += __shfl_down_sync(0xffffffffu, s[c], off, 8);
        if (l == 0) {
            #pragma unroll
            for (int c = 0; c < 5; c++) g_WfoldT[c*256 + t] = s[c];
        }
    } else {
        if (tid < 5) {
            float s = b_out[tid];
            for (int k = 0; k < 512; k++) s += b3[k] * W_out[k*5 + tid];
            g_bfold[tid] = s;
        }
        if (tid == 32) g_acc = 0.0;
    }
}

// ---------------- tf32 tensor-core SGEMM v3 ----------------
// C[4096,256] = act(A1@W1 [+ A2@W2] + bias [+ rowBias])
// BM=64, BN=64, BK=64, 256 threads (8 warps, 2m x 4n), cp.async double-buffered.
// Raw fp32 bits fed to tf32 MMA (truncation).
#define APAD 68
#define WPAD 72
__global__ void __launch_bounds__(256)
sgemm_tc(const float* __restrict__ A1, const float* __restrict__ W1, int K1,
         const float* __restrict__ A2, const float* __restrict__ W2, int K2,
         const float* __restrict__ bias, const float* __restrict__ rowBias,
         float* __restrict__ C, int doRelu)
{
    extern __shared__ float sm[];
    float* Asm = sm;                   // [2][64][APAD]  (row m, inner k)
    float* Wsm = sm + 2*64*APAD;       // [2][64][WPAD]  (row k, inner n)

    int tid = threadIdx.x;
    int wid = tid >> 5;
    int lane = tid & 31;
    int warp_m = wid & 1;              // 0..1 -> 32 rows each
    int warp_n = wid >> 1;             // 0..3 -> 16 cols each
    int gi = lane >> 2;                // 0..7
    int tg = lane & 3;                 // 0..3

    int m0 = blockIdx.y * 64;
    int n0 = blockIdx.x * 64;

    float acc[2][2][4];
    #pragma unroll
    for (int mt = 0; mt < 2; mt++)
        #pragma unroll
        for (int nt = 0; nt < 2; nt++)
            #pragma unroll
            for (int q = 0; q < 4; q++) acc[mt][nt][q] = 0.f;

    // per-thread load indices: 4 float4 for A, 4 for W
    int lr[4], lc[4];
    #pragma unroll
    for (int i = 0; i < 4; i++) { int f = tid + i*256; lr[i] = f >> 4; lc[i] = (f & 15) * 4; }

    for (int pass = 0; pass < 2; pass++) {
        const float* A = pass ? A2 : A1;
        const float* W = pass ? W2 : W1;
        int K = pass ? K2 : K1;
        if (K == 0) break;
        int nit = K >> 6;

        // prefetch iter 0 into buf 0
        #pragma unroll
        for (int i = 0; i < 4; i++) {
            cp_async16(&Asm[0*64*APAD + lr[i]*APAD + lc[i]],
                       &A[(size_t)(m0 + lr[i])*K + lc[i]]);
            cp_async16(&Wsm[0*64*WPAD + lr[i]*WPAD + lc[i]],
                       &W[(size_t)lr[i]*256 + n0 + lc[i]]);
        }
        cp_commit();

        for (int it = 0; it < nit; it++) {
            int cur = it & 1;
            if (it + 1 < nit) {
                int nb = cur ^ 1;
                int k0n = (it + 1) << 6;
                #pragma unroll
                for (int i = 0; i < 4; i++) {
                    cp_async16(&Asm[nb*64*APAD + lr[i]*APAD + lc[i]],
                               &A[(size_t)(m0 + lr[i])*K + k0n + lc[i]]);
                    cp_async16(&Wsm[nb*64*WPAD + lr[i]*WPAD + lc[i]],
                               &W[(size_t)(k0n + lr[i])*256 + n0 + lc[i]]);
                }
                cp_commit();
                cp_wait<1>();
            } else {
                cp_wait<0>();
            }
            __syncthreads();

            const float* Ab = Asm + cur*64*APAD;
            const float* Wb = Wsm + cur*64*WPAD;
            #pragma unroll
            for (int kb = 0; kb < 8; kb++) {
                int k8 = kb*8;
                uint32_t a[2][4];
                #pragma unroll
                for (int mt = 0; mt < 2; mt++) {
                    int m = warp_m*32 + mt*16 + gi;
                    a[mt][0] = __float_as_uint(Ab[(m    )*APAD + k8 + tg    ]);
                    a[mt][1] = __float_as_uint(Ab[(m + 8)*APAD + k8 + tg    ]);
                    a[mt][2] = __float_as_uint(Ab[(m    )*APAD + k8 + tg + 4]);
                    a[mt][3] = __float_as_uint(Ab[(m + 8)*APAD + k8 + tg + 4]);
                }
                #pragma unroll
                for (int nt = 0; nt < 2; nt++) {
                    int n = warp_n*16 + nt*8 + gi;
                    uint32_t b0 = __float_as_uint(Wb[(k8 + tg    )*WPAD + n]);
                    uint32_t b1 = __float_as_uint(Wb[(k8 + tg + 4)*WPAD + n]);
                    #pragma unroll
                    for (int mt = 0; mt < 2; mt++)
                        mma_tf32(acc[mt][nt][0], acc[mt][nt][1], acc[mt][nt][2], acc[mt][nt][3],
                                 a[mt][0], a[mt][1], a[mt][2], a[mt][3], b0, b1);
                }
            }
            __syncthreads();
        }
    }

    // epilogue
    #pragma unroll
    for (int mt = 0; mt < 2; mt++) {
        #pragma unroll
        for (int half = 0; half < 2; half++) {
            int m = m0 + warp_m*32 + mt*16 + gi + half*8;
            #pragma unroll
            for (int nt = 0; nt < 2; nt++) {
                int n = n0 + warp_n*16 + nt*8 + tg*2;
                float v0 = acc[mt][nt][half*2 + 0];
                float v1 = acc[mt][nt][half*2 + 1];
                if (bias)    { v0 += bias[n]; v1 += bias[n+1]; }
                if (rowBias) {
                    const float* rb = rowBias + ((m >> 6) << 8);
                    v0 += rb[n]; v1 += rb[n+1];
                }
                if (doRelu)  { v0 = fmaxf(v0, 0.f); v1 = fmaxf(v1, 0.f); }
                *(float2*)&C[(size_t)m*256 + n] = make_float2(v0, v1);
            }
        }
    }
}

// ---------------- edge scatter: agg[dst] += relu(Hm[src] + b_msg + ea@We) ----------
__global__ void __launch_bounds__(256)
edge_scatter(const int* __restrict__ src, const int* __restrict__ dst,
             const float* __restrict__ ea, const float* __restrict__ W_msg,
             const float* __restrict__ b_msg, const float* __restrict__ Hm,
             float* __restrict__ agg, int E)
{
    __shared__ float We[5][256];
    __shared__ float bm[256];
    __shared__ float eas[64][5];
    __shared__ int   ss[64], ds[64];
    int tid = threadIdx.x;
    const float* Wep = W_msg + 256*256;
    for (int i = tid; i < 5*256; i += 256) ((float*)We)[i] = Wep[i];
    bm[tid] = b_msg[tid];
    int e0 = blockIdx.x * 64;
    if (tid < 64 && e0 + tid < E) { ss[tid] = src[e0+tid]; ds[tid] = dst[e0+tid]; }
    for (int i = tid; i < 320; i += 256) {
        if ((size_t)e0*5 + i < (size_t)E*5) eas[i/5][i%5] = ea[(size_t)e0*5 + i];
    }
    __syncthreads();
    #pragma unroll 4
    for (int q = 0; q < 64; q++) {
        int e = e0 + q;
        if (e >= E) break;
        float v = bm[tid]
                + eas[q][0]*We[0][tid] + eas[q][1]*We[1][tid] + eas[q][2]*We[2][tid]
                + eas[q][3]*We[3][tid] + eas[q][4]*We[4][tid]
                + Hm[(size_t)ss[q]*256 + tid];
        v = fmaxf(v, 0.f);
        atomicAdd(&agg[(size_t)ds[q]*256 + tid], v);
    }
}

// ---------------- pair megakernel (tensor-core h2 GEMM) ----------------
__global__ void __launch_bounds__(256, 2)
pair_kernel(const float* __restrict__ Ag, const float* __restrict__ Bg,
            const int* __restrict__ sel_b, const int* __restrict__ sel_i,
            const int* __restrict__ sel_j, const int* __restrict__ golden,
            const float* __restrict__ W2, const float* __restrict__ b2)
{
    extern __shared__ uint32_t smem[];
    uint32_t* h1u = smem;                   // [64][260] fp32 bits, reused as fp32 h2
    uint32_t* w2u = h1u + 64*260;           // [32][260] fp32 bits
    float*    wfs = (float*)(w2u + 32*260); // [5][256]
    float*    b2s = wfs + 5*256;            // [256]
    float*    bfs = b2s + 256;              // [8]
    float*    h1f = (float*)h1u;

    int tid  = threadIdx.x;
    int wid  = tid >> 5;
    int lane = tid & 31;
    int warp_m = wid & 1;                  // 0..1
    int warp_n = wid >> 1;                 // 0..3
    int gi = lane >> 2;
    int tg = lane & 3;
    int e0 = blockIdx.x * 64;

    for (int i = tid; i < 5*256; i += 256) wfs[i] = g_WfoldT[i];
    b2s[tid] = b2[tid];
    if (tid < 5) bfs[tid] = g_bfold[tid];

    // gather phase: h1 = relu(A[bi*64+si] + B[bi*64+sj])
    #pragma unroll
    for (int t = 0; t < 8; t++) {
        int r = wid*8 + t;
        int e = e0 + r;
        int bsel = sel_b[e];
        int ii = bsel*64 + sel_i[e];
        int jj = bsel*64 + sel_j[e];
        const float* ap = Ag + (size_t)ii*256;
        const float* bp = Bg + (size_t)jj*256;
        #pragma unroll
        for (int q = 0; q < 2; q++) {
            int c = lane*4 + q*128;
            float4 av = *(const float4*)(ap + c);
            float4 bv = *(const float4*)(bp + c);
            h1u[r*260 + c + 0] = __float_as_uint(fmaxf(av.x + bv.x, 0.f));
            h1u[r*260 + c + 1] = __float_as_uint(fmaxf(av.y + bv.y, 0.f));
            h1u[r*260 + c + 2] = __float_as_uint(fmaxf(av.z + bv.z, 0.f));
            h1u[r*260 + c + 3] = __float_as_uint(fmaxf(av.w + bv.w, 0.f));
        }
    }
    __syncthreads();

    float acc[2][8][4];
    #pragma unroll
    for (int mt = 0; mt < 2; mt++)
        #pragma unroll
        for (int nt = 0; nt < 8; nt++)
            #pragma unroll
            for (int q = 0; q < 4; q++) acc[mt][nt][q] = 0.f;

    for (int k0 = 0; k0 < 256; k0 += 32) {
        #pragma unroll
        for (int i = 0; i < 8; i++) {
            int f  = tid + i*256;
            int k  = f >> 6;
            int nq = (f & 63) * 4;
            float4 v = *(const float4*)&W2[(size_t)(k0 + k)*256 + nq];
            w2u[k*260 + nq + 0] = __float_as_uint(v.x);
            w2u[k*260 + nq + 1] = __float_as_uint(v.y);
            w2u[k*260 + nq + 2] = __float_as_uint(v.z);
            w2u[k*260 + nq + 3] = __float_as_uint(v.w);
        }
        __syncthreads();
        #pragma unroll
        for (int ks = 0; ks < 4; ks++) {
            int kb = ks*8;
            uint32_t a[2][4];
            #pragma unroll
            for (int mt = 0; mt < 2; mt++) {
                int m = warp_m*32 + mt*16 + gi;
                a[mt][0] = h1u[(m    )*260 + k0 + kb + tg    ];
                a[mt][1] = h1u[(m + 8)*260 + k0 + kb + tg    ];
                a[mt][2] = h1u[(m    )*260 + k0 + kb + tg + 4];
                a[mt][3] = h1u[(m + 8)*260 + k0 + kb + tg + 4];
            }
            #pragma unroll
            for (int nt = 0; nt < 8; nt++) {
                int n = warp_n*64 + nt*8 + gi;
                uint32_t b0 = w2u[(kb + tg    )*260 + n];
                uint32_t b1 = w2u[(kb + tg + 4)*260 + n];
                #pragma unroll
                for (int mt = 0; mt < 2; mt++)
                    mma_tf32(acc[mt][nt][0], acc[mt][nt][1], acc[mt][nt][2], acc[mt][nt][3],
                             a[mt][0], a[mt][1], a[mt][2], a[mt][3], b0, b1);
            }
        }
        __syncthreads();
    }

    // h2 = relu(acc + b2)
    #pragma unroll
    for (int mt = 0; mt < 2; mt++) {
        #pragma unroll
        for (int half = 0; half < 2; half++) {
            int m = warp_m*32 + mt*16 + gi + half*8;
            #pragma unroll
            for (int nt = 0; nt < 8; nt++) {
                int n = warp_n*64 + nt*8 + tg*2;
                float v0 = fmaxf(acc[mt][nt][half*2 + 0] + b2s[n],     0.f);
                float v1 = fmaxf(acc[mt][nt][half*2 + 1] + b2s[n + 1], 0.f);
                h1f[m*260 + n]     = v0;
                h1f[m*260 + n + 1] = v1;
            }
        }
    }
    __syncthreads();

    // logits + loss
    double lsum = 0.0;
    for (int t = 0; t < 8; t++) {
        int r = wid*8 + t;
        float p[5] = {0.f,0.f,0.f,0.f,0.f};
        #pragma unroll
        for (int m8 = 0; m8 < 8; m8++) {
            int k = lane + 32*m8;
            float hv = h1f[r*260 + k];
            #pragma unroll
            for (int c = 0; c < 5; c++) p[c] += hv * wfs[c*256 + k];
        }
        #pragma unroll
        for (int off = 16; off; off >>= 1)
            #pragma unroll
            for (int c = 0; c < 5; c++) p[c] += __shfl_xor_sync(0xffffffffu, p[c], off);
        if (lane == 0) {
            float lg[5], mx = -1e30f;
            #pragma unroll
            for (int c = 0; c < 5; c++) { lg[c] = p[c] + bfs[c]; mx = fmaxf(mx, lg[c]); }
            float s = 0.f;
            #pragma unroll
            for (int c = 0; c < 5; c++) s += expf(lg[c] - mx);
            float lse = mx + logf(s);
            int gold = golden[e0 + r];
            lsum += (double)(lse - lg[gold]);
        }
    }
    if (lane == 0) atomicAdd(&g_acc, lsum);
}

// ---------------- finalize ----------------
__global__ void finalize_kernel(float* __restrict__ out, int esel)
{
    out[0] = (float)(g_acc / (double)esel);
}

// ---------------- host launcher ----------------
extern "C" void kernel_launch(void* const* d_in, const int* in_sizes, int n_in,
                              void* d_out, int out_size)
{
    const float* x         = (const float*)d_in[0];
    const int*   eidx      = (const int*)  d_in[1];
    const float* edge_attr = (const float*)d_in[2];
    const float* props     = (const float*)d_in[3];
    const int*   sel_b     = (const int*)  d_in[4];
    const int*   sel_i     = (const int*)  d_in[5];
    const int*   sel_j     = (const int*)  d_in[6];
    const int*   golden    = (const int*)  d_in[7];
    const float* W_prop = (const float*)d_in[8];
    const float* b_prop = (const float*)d_in[9];
    const float* W_in   = (const float*)d_in[10];
    const float* b_in   = (const float*)d_in[11];
    const float* W_msg  = (const float*)d_in[12];
    const float* b_msg  = (const float*)d_in[13];
    const float* W_upd  = (const float*)d_in[14];
    const float* b_upd  = (const float*)d_in[15];
    const float* W_add  = (const float*)d_in[16];
    const float* b_add  = (const float*)d_in[17];
    const float* W1     = (const float*)d_in[18];
    const float* b1     = (const float*)d_in[19];
    const float* W2     = (const float*)d_in[20];
    const float* b2     = (const float*)d_in[21];
    const float* W3     = (const float*)d_in[22];
    const float* b3     = (const float*)d_in[23];
    const float* W_out  = (const float*)d_in[24];
    const float* b_out  = (const float*)d_in[25];

    int E    = in_sizes[1] / 2;
    int ESEL = in_sizes[4];
    const int* src = eidx;
    const int* dst = eidx + E;

    float *p_h, *p_ht, *p_agg, *p_embg, *p_A, *p_B, *p_Hm, *p_propadd;
    cudaGetSymbolAddress((void**)&p_h,    g_h);
    cudaGetSymbolAddress((void**)&p_ht,   g_ht);
    cudaGetSymbolAddress((void**)&p_agg,  g_agg);
    cudaGetSymbolAddress((void**)&p_embg, g_embg);
    cudaGetSymbolAddress((void**)&p_A,    g_A);
    cudaGetSymbolAddress((void**)&p_B,    g_B);
    cudaGetSymbolAddress((void**)&p_Hm,   g_Hm);
    cudaGetSymbolAddress((void**)&p_propadd, g_propadd);

    int gemmSmem = (2*64*APAD + 2*64*WPAD) * (int)sizeof(float);  // 71680
    cudaFuncSetAttribute(sgemm_tc, cudaFuncAttributeMaxDynamicSharedMemorySize, gemmSmem);
    int pairSmem = (64*260 + 32*260 + 5*256 + 256 + 8) * (int)sizeof(float);
    cudaFuncSetAttribute(pair_kernel, cudaFuncAttributeMaxDynamicSharedMemorySize, pairSmem);

    dim3 gemmGrid(4, BNODES/64);   // (n-tiles, m-tiles) = (4, 64) = 256 CTAs

    setup_kernel<<<73, 256>>>(W3, b3, W_out, b_out, props, W_prop, b_prop, W_add, b_add);

    // h0 = relu(x @ W_in + b_in)
    sgemm_tc<<<gemmGrid, 256, gemmSmem>>>(x, W_in, 192, nullptr, nullptr, 0, b_in, nullptr, p_h, 1);

    float* cur = p_h;
    float* nxt = p_ht;
    for (int t = 0; t < 4; t++) {
        cudaMemsetAsync(p_agg, 0, (size_t)BNODES*HDIM*sizeof(float));
        // Hm = h @ W_msg[0:256]
        sgemm_tc<<<gemmGrid, 256, gemmSmem>>>(cur, W_msg, 256, nullptr, nullptr, 0, nullptr, nullptr, p_Hm, 0);
        // agg[dst] += relu(Hm[src] + b_msg + ea@We)
        edge_scatter<<<(E + 63)/64, 256>>>(src, dst, edge_attr, W_msg, b_msg, p_Hm, p_agg, E);
        // h = relu(h@W_upd_top + agg@W_upd_bot + b_upd)
        sgemm_tc<<<gemmGrid, 256, gemmSmem>>>(cur, W_upd, 256, p_agg, W_upd + 256*256, 256,
                                              b_upd, nullptr, nxt, 1);
        float* tmp = cur; cur = nxt; nxt = tmp;
    }

    // embg = h @ W_add[0:256] + propadd[b]   (no relu)
    sgemm_tc<<<gemmGrid, 256, gemmSmem>>>(cur, W_add, 256, nullptr, nullptr, 0, nullptr, p_propadd, p_embg, 0);

    // A = embg @ W1[0:256] + b1 ; B = embg @ W1[256:512]
    sgemm_tc<<<gemmGrid, 256, gemmSmem>>>(p_embg, W1, 256, nullptr, nullptr, 0, b1, nullptr, p_A, 0);
    sgemm_tc<<<gemmGrid, 256, gemmSmem>>>(p_embg, W1 + 256*256, 256, nullptr, nullptr, 0, nullptr, nullptr, p_B, 0);

    // pair stage + loss
    pair_kernel<<<ESEL/64, 256, pairSmem>>>(p_A, p_B, sel_b, sel_i, sel_j, golden, W2, b2);

    finalize_kernel<<<1, 1>>>((float*)d_out, ESEL);
}